// round 6
// baseline (speedup 1.0000x reference)
#include <cuda_runtime.h>
#include <cuda_bf16.h>

#define NN 100000
#define NE 1000000
#define NG 512
#define HID 64

// ---------------- scratch (static device globals; no allocation) ------------
__device__ int    g_is64;
__device__ int    g_src[NE];
__device__ int    g_dst[NE];
__device__ int    g_batch[NN];
__device__ float  g_deg[NN];
__device__ float  g_dinv[NN];
__device__ float  g_norm[NE];
__device__ float4 g_hw4[NN * 16];    // [N,64] as 16x float4 per node
__device__ float4 g_agg4[NN * 16];
__device__ float4 g_h4[NN * 16];
__device__ float4 g_sums4[NG * 16];
__device__ float  g_counts[NG];

// vector reduction (no-return atomic add), sm_90+
__device__ __forceinline__ void red_add_v4(float4* a, float4 v) {
    asm volatile("red.global.add.v4.f32 [%0], {%1,%2,%3,%4};"
                 :: "l"(a), "f"(v.x), "f"(v.y), "f"(v.z), "f"(v.w)
                 : "memory");
}

// ---------------- kernels ---------------------------------------------------

// Decide whether index buffers are int64 or int32. Reading 64 bytes is safe
// under either dtype (buffer is >= 8MB). True int64 node ids are all < NN;
// int32 data misread as int64 has a random high word (8x zero ~ p=1e-40).
__global__ void k_detect(const void* ei_raw) {
    const long long* p = (const long long*)ei_raw;
    int ok = 1;
#pragma unroll
    for (int i = 0; i < 8; i++) {
        long long v = p[i];
        if (v < 0 || v >= NN) ok = 0;
    }
    g_is64 = ok;
}

__global__ void k_init() {
    int i = blockIdx.x * blockDim.x + threadIdx.x;
    if (i < NN)      g_deg[i] = 1.0f;          // self-loop contributes 1
    if (i < NG * 16) g_sums4[i] = make_float4(0.f, 0.f, 0.f, 0.f);
    if (i < NG)      g_counts[i] = 0.0f;
}

// Convert edge_index + batch to int32 scratch; accumulate degree.
__global__ void k_cvt(const void* ei_raw, const void* batch_raw) {
    int i = blockIdx.x * blockDim.x + threadIdx.x;
    int is64 = g_is64;
    if (i < NE) {
        int s, d;
        if (is64) {
            const long long* p = (const long long*)ei_raw;
            s = (int)p[i]; d = (int)p[NE + i];
        } else {
            const int* p = (const int*)ei_raw;
            s = p[i]; d = p[NE + i];
        }
        g_src[i] = s;
        g_dst[i] = d;
        atomicAdd(&g_deg[d], 1.0f);
    }
    if (i < NN) {
        int b = is64 ? (int)((const long long*)batch_raw)[i]
                     : ((const int*)batch_raw)[i];
        g_batch[i] = b;
        atomicAdd(&g_counts[b], 1.0f);
    }
}

__global__ void k_dinv() {
    int i = blockIdx.x * blockDim.x + threadIdx.x;
    if (i < NN) g_dinv[i] = rsqrtf(g_deg[i]);
}

__global__ void k_norm() {
    int e = blockIdx.x * blockDim.x + threadIdx.x;
    if (e < NE) g_norm[e] = g_dinv[g_src[e]] * g_dinv[g_dst[e]];
}

// hw = x @ W1   (x: [N,3], W1: [3,64]); also zeroes agg for layer 1
__global__ void k_xw1(const float* __restrict__ x, const float* __restrict__ W1) {
    int t = blockIdx.x * blockDim.x + threadIdx.x;
    if (t >= NN * 16) return;
    int n = t >> 4, c = t & 15;
    float x0 = __ldg(x + n * 3 + 0);
    float x1 = __ldg(x + n * 3 + 1);
    float x2 = __ldg(x + n * 3 + 2);
    float4 w0 = __ldg((const float4*)(W1)        + c);
    float4 w1 = __ldg((const float4*)(W1 + 64)   + c);
    float4 w2 = __ldg((const float4*)(W1 + 128)  + c);
    float4 o;
    o.x = x0 * w0.x + x1 * w1.x + x2 * w2.x;
    o.y = x0 * w0.y + x1 * w1.y + x2 * w2.y;
    o.z = x0 * w0.z + x1 * w1.z + x2 * w2.z;
    o.w = x0 * w0.w + x1 * w1.w + x2 * w2.w;
    g_hw4[t] = o;
    g_agg4[t] = make_float4(0.f, 0.f, 0.f, 0.f);
}

// per (edge, 4-feature chunk): agg[dst] += hw[src] * norm[e]
__global__ void k_scatter() {
    int t = blockIdx.x * blockDim.x + threadIdx.x;
    if (t >= NE * 16) return;
    int e = t >> 4, c = t & 15;
    int s = __ldg(g_src + e);
    int d = __ldg(g_dst + e);
    float w = __ldg(g_norm + e);
    float4 v = __ldg(&g_hw4[s * 16 + c]);
    v.x *= w; v.y *= w; v.z *= w; v.w *= w;
    red_add_v4(&g_agg4[d * 16 + c], v);
}

// h = relu(agg + hw * dinv^2 + b)   -> writes g_h4
__global__ void k_relu1(const float* __restrict__ b) {
    int t = blockIdx.x * blockDim.x + threadIdx.x;
    if (t >= NN * 16) return;
    int n = t >> 4, c = t & 15;
    float di = g_dinv[n];
    float sl = di * di;
    float4 a  = g_agg4[t];
    float4 hw = g_hw4[t];
    float4 bb = __ldg((const float4*)b + c);
    float4 o;
    o.x = fmaxf(a.x + hw.x * sl + bb.x, 0.f);
    o.y = fmaxf(a.y + hw.y * sl + bb.y, 0.f);
    o.z = fmaxf(a.z + hw.z * sl + bb.z, 0.f);
    o.w = fmaxf(a.w + hw.w * sl + bb.w, 0.f);
    g_h4[t] = o;
}

// hw = h @ W2  (h: [N,64], W2: [64,64]); 64 nodes/block; also zeroes agg
__global__ void k_gemm(const float* __restrict__ W2) {
    __shared__ float sW[64 * 64];
    __shared__ float sh[64 * 65];     // padded to kill bank conflicts
    int t = threadIdx.x;
    int base = blockIdx.x * 64;

    float4* sW4 = (float4*)sW;
    const float4* W24 = (const float4*)W2;
    for (int i = t; i < 1024; i += 256) sW4[i] = __ldg(W24 + i);

    const float* hflat = (const float*)g_h4;
    for (int i = t; i < 4096; i += 256) {
        int nl = i >> 6, k = i & 63;
        int n = base + nl;
        sh[nl * 65 + k] = (n < NN) ? hflat[n * 64 + k] : 0.f;
    }
    __syncthreads();

    int fg = t & 15, ns = t >> 4;   // fg: 4-feat group, ns: node slot (x4 nodes)
    float4 acc[4];
#pragma unroll
    for (int i = 0; i < 4; i++) acc[i] = make_float4(0.f, 0.f, 0.f, 0.f);

#pragma unroll 8
    for (int k = 0; k < 64; k++) {
        float4 w = sW4[k * 16 + fg];
#pragma unroll
        for (int i = 0; i < 4; i++) {
            float hv = sh[(ns * 4 + i) * 65 + k];
            acc[i].x += hv * w.x;
            acc[i].y += hv * w.y;
            acc[i].z += hv * w.z;
            acc[i].w += hv * w.w;
        }
    }
#pragma unroll
    for (int i = 0; i < 4; i++) {
        int n = base + ns * 4 + i;
        if (n < NN) {
            g_hw4[n * 16 + fg] = acc[i];
            g_agg4[n * 16 + fg] = make_float4(0.f, 0.f, 0.f, 0.f);
        }
    }
}

// final: relu(agg + hw*dinv^2 + b2), then pool-add into sums[batch[n]]
__global__ void k_final(const float* __restrict__ b2) {
    int t = blockIdx.x * blockDim.x + threadIdx.x;
    if (t >= NN * 16) return;
    int n = t >> 4, c = t & 15;
    float di = g_dinv[n];
    float sl = di * di;
    float4 a  = g_agg4[t];
    float4 hw = g_hw4[t];
    float4 bb = __ldg((const float4*)b2 + c);
    float4 o;
    o.x = fmaxf(a.x + hw.x * sl + bb.x, 0.f);
    o.y = fmaxf(a.y + hw.y * sl + bb.y, 0.f);
    o.z = fmaxf(a.z + hw.z * sl + bb.z, 0.f);
    o.w = fmaxf(a.w + hw.w * sl + bb.w, 0.f);
    int g = __ldg(g_batch + n);
    red_add_v4(&g_sums4[g * 16 + c], o);
}

__global__ void k_out(float4* __restrict__ out) {
    int t = blockIdx.x * blockDim.x + threadIdx.x;
    if (t >= NG * 16) return;
    int g = t >> 4;
    float inv = 1.0f / fmaxf(g_counts[g], 1.0f);
    float4 s = g_sums4[t];
    out[t] = make_float4(s.x * inv, s.y * inv, s.z * inv, s.w * inv);
}

// ---------------- launch ----------------------------------------------------

extern "C" void kernel_launch(void* const* d_in, const int* in_sizes, int n_in,
                              void* d_out, int out_size) {
    // Resolve inputs by element count (robust to metadata ordering and to
    // int64-vs-int32 index dtype; 4000000/200000 cover "int32 view of int64").
    const float* x     = nullptr;
    const float* W1    = nullptr;
    const float* b1    = nullptr;
    const float* W2    = nullptr;
    const float* b2    = nullptr;
    const void*  ei    = nullptr;
    const void*  batch = nullptr;

    for (int i = 0; i < n_in; i++) {
        int sz = in_sizes[i];
        const void* p = d_in[i];
        switch (sz) {
            case 300000:  x     = (const float*)p; break;
            case 192:     W1    = (const float*)p; break;
            case 4096:    W2    = (const float*)p; break;
            case 2000000:
            case 4000000: ei    = p; break;
            case 100000:
            case 200000:  batch = p; break;
            case 64:
                if (!b1) b1 = (const float*)p;
                else     b2 = (const float*)p;
                break;
            default: break;
        }
    }

    const int TB = 256;
    const int gN   = (NN + TB - 1) / TB;            // 391
    const int gE   = (NE + TB - 1) / TB;            // 3907
    const int gN16 = (NN * 16 + TB - 1) / TB;       // 6250
    const int gE16 = (NE * 16 + TB - 1) / TB;       // 62500
    const int gG   = (NG * 16 + TB - 1) / TB;       // 32
    const int gGemm = (NN + 63) / 64;               // 1563

    k_detect<<<1, 1>>>(ei);
    k_init<<<gN, TB>>>();
    k_cvt<<<gE, TB>>>(ei, batch);
    k_dinv<<<gN, TB>>>();
    k_norm<<<gE, TB>>>();

    // layer 1
    k_xw1<<<gN16, TB>>>(x, W1);          // also zeroes agg
    k_scatter<<<gE16, TB>>>();
    k_relu1<<<gN16, TB>>>(b1);

    // layer 2
    k_gemm<<<gGemm, TB>>>(W2);           // also zeroes agg
    k_scatter<<<gE16, TB>>>();
    k_final<<<gN16, TB>>>(b2);

    k_out<<<gG, TB>>>((float4*)d_out);
}

// round 8
// speedup vs baseline: 2.0605x; 2.0605x over previous
#include <cuda_runtime.h>
#include <cuda_bf16.h>

#define NN 100000
#define NE 1000000
#define NG 512
#define HID 64
#define NBLK 98   // ceil(NN/1024)

// ---------------- scratch (static device globals; no allocation) ------------
__device__ int    g_is64;
__device__ int    g_src[NE];
__device__ int    g_dst[NE];
__device__ int    g_batch[NN];
__device__ int    g_indeg[NN];
__device__ int    g_rowtmp[NN];
__device__ int    g_rowstart[NN];
__device__ int    g_cursor[NN];
__device__ int    g_blk[NBLK];
__device__ unsigned long long g_csr[NE];   // packed (norm<<32 | src)
__device__ float  g_dinv[NN];
__device__ float4 g_hw4[NN * 16];    // [N,64] as 16x float4 per node
__device__ float4 g_h4[NN * 16];
__device__ float4 g_sums4[NG * 16];
__device__ float  g_counts[NG];

// vector reduction (no-return atomic add), sm_90+
__device__ __forceinline__ void red_add_v4(float4* a, float4 v) {
    asm volatile("red.global.add.v4.f32 [%0], {%1,%2,%3,%4};"
                 :: "l"(a), "f"(v.x), "f"(v.y), "f"(v.z), "f"(v.w)
                 : "memory");
}

// ---------------- setup kernels ---------------------------------------------

// Detect int64 vs int32 index buffers (reading 64B is safe either way).
__global__ void k_detect(const void* ei_raw) {
    const long long* p = (const long long*)ei_raw;
    int ok = 1;
#pragma unroll
    for (int i = 0; i < 8; i++) {
        long long v = p[i];
        if (v < 0 || v >= NN) ok = 0;
    }
    g_is64 = ok;
}

__global__ void k_init() {
    int i = blockIdx.x * blockDim.x + threadIdx.x;
    if (i < NN)      g_indeg[i] = 0;
    if (i < NG * 16) g_sums4[i] = make_float4(0.f, 0.f, 0.f, 0.f);
    if (i < NG)      g_counts[i] = 0.0f;
}

// Convert edge_index + batch to int32 scratch; accumulate in-degree & counts.
__global__ void k_cvt(const void* ei_raw, const void* batch_raw) {
    int i = blockIdx.x * blockDim.x + threadIdx.x;
    int is64 = g_is64;
    if (i < NE) {
        int s, d;
        if (is64) {
            const long long* p = (const long long*)ei_raw;
            s = (int)p[i]; d = (int)p[NE + i];
        } else {
            const int* p = (const int*)ei_raw;
            s = p[i]; d = p[NE + i];
        }
        g_src[i] = s;
        g_dst[i] = d;
        atomicAdd(&g_indeg[d], 1);
    }
    if (i < NN) {
        int b = is64 ? (int)((const long long*)batch_raw)[i]
                     : ((const int*)batch_raw)[i];
        g_batch[i] = b;
        atomicAdd(&g_counts[b], 1.0f);
    }
}

__global__ void k_dinv() {
    int i = blockIdx.x * blockDim.x + threadIdx.x;
    if (i < NN) g_dinv[i] = rsqrtf((float)g_indeg[i] + 1.0f);  // +1 self loop
}

// ---- 3-step exclusive scan of g_indeg -> g_rowstart ------------------------

__global__ void k_scan1() {
    __shared__ int sh[1024];
    int n = blockIdx.x * 1024 + threadIdx.x;
    int v = (n < NN) ? g_indeg[n] : 0;
    sh[threadIdx.x] = v;
    __syncthreads();
#pragma unroll
    for (int off = 1; off < 1024; off <<= 1) {
        int cur = sh[threadIdx.x];
        int add = (threadIdx.x >= off) ? sh[threadIdx.x - off] : 0;
        __syncthreads();
        sh[threadIdx.x] = cur + add;
        __syncthreads();
    }
    if (n < NN) g_rowtmp[n] = sh[threadIdx.x] - v;   // exclusive within block
    if (threadIdx.x == 1023) g_blk[blockIdx.x] = sh[1023];
}

__global__ void k_scan2() {
    int acc = 0;
    for (int i = 0; i < NBLK; i++) { int v = g_blk[i]; g_blk[i] = acc; acc += v; }
}

__global__ void k_scan3() {
    int n = blockIdx.x * blockDim.x + threadIdx.x;
    if (n < NN) {
        int row = g_rowtmp[n] + g_blk[n >> 10];
        g_rowstart[n] = row;
        g_cursor[n]   = row;
    }
}

// Place each edge into the dst-ordered CSR with its precomputed norm.
__global__ void k_place() {
    int e = blockIdx.x * blockDim.x + threadIdx.x;
    if (e >= NE) return;
    int s = g_src[e], d = g_dst[e];
    float w = g_dinv[s] * g_dinv[d];
    int pos = atomicAdd(&g_cursor[d], 1);
    g_csr[pos] = ((unsigned long long)__float_as_uint(w) << 32) | (unsigned)s;
}

// ---------------- compute kernels -------------------------------------------

// hw = x @ W1   (x: [N,3], W1: [3,64])
__global__ void k_xw1(const float* __restrict__ x, const float* __restrict__ W1) {
    int t = blockIdx.x * blockDim.x + threadIdx.x;
    if (t >= NN * 16) return;
    int n = t >> 4, c = t & 15;
    float x0 = __ldg(x + n * 3 + 0);
    float x1 = __ldg(x + n * 3 + 1);
    float x2 = __ldg(x + n * 3 + 2);
    float4 w0 = __ldg((const float4*)(W1)       + c);
    float4 w1 = __ldg((const float4*)(W1 + 64)  + c);
    float4 w2 = __ldg((const float4*)(W1 + 128) + c);
    float4 o;
    o.x = x0 * w0.x + x1 * w1.x + x2 * w2.x;
    o.y = x0 * w0.y + x1 * w1.y + x2 * w2.y;
    o.z = x0 * w0.z + x1 * w1.z + x2 * w2.z;
    o.w = x0 * w0.w + x1 * w1.w + x2 * w2.w;
    g_hw4[t] = o;
}

// Pull aggregation, layer 1: h = relu(sum_in hw[s]*w + hw[n]*dinv^2 + b1)
__global__ void k_agg1(const float* __restrict__ b) {
    int t = blockIdx.x * blockDim.x + threadIdx.x;
    if (t >= NN * 16) return;
    int n = t >> 4, c = t & 15;
    int row = __ldg(g_rowstart + n);
    int cnt = __ldg(g_indeg + n);
    float4 acc = make_float4(0.f, 0.f, 0.f, 0.f);
    for (int i = row; i < row + cnt; i++) {
        unsigned long long pk = __ldg(&g_csr[i]);
        int   s = (int)(unsigned)pk;
        float w = __uint_as_float((unsigned)(pk >> 32));
        float4 v = __ldg(&g_hw4[s * 16 + c]);
        acc.x += v.x * w; acc.y += v.y * w;
        acc.z += v.z * w; acc.w += v.w * w;
    }
    float di = g_dinv[n];
    float sl = di * di;
    float4 hw = g_hw4[t];
    float4 bb = __ldg((const float4*)b + c);
    float4 o;
    o.x = fmaxf(acc.x + hw.x * sl + bb.x, 0.f);
    o.y = fmaxf(acc.y + hw.y * sl + bb.y, 0.f);
    o.z = fmaxf(acc.z + hw.z * sl + bb.z, 0.f);
    o.w = fmaxf(acc.w + hw.w * sl + bb.w, 0.f);
    g_h4[t] = o;
}

// hw = h @ W2  (h: [N,64], W2: [64,64]); 64 nodes/block
__global__ void k_gemm(const float* __restrict__ W2) {
    __shared__ float sW[64 * 64];
    __shared__ float sh[64 * 65];     // padded to kill bank conflicts
    int t = threadIdx.x;
    int base = blockIdx.x * 64;

    float4* sW4 = (float4*)sW;
    const float4* W24 = (const float4*)W2;
    for (int i = t; i < 1024; i += 256) sW4[i] = __ldg(W24 + i);

    const float* hflat = (const float*)g_h4;
    for (int i = t; i < 4096; i += 256) {
        int nl = i >> 6, k = i & 63;
        int n = base + nl;
        sh[nl * 65 + k] = (n < NN) ? hflat[n * 64 + k] : 0.f;
    }
    __syncthreads();

    int fg = t & 15, ns = t >> 4;
    float4 acc[4];
#pragma unroll
    for (int i = 0; i < 4; i++) acc[i] = make_float4(0.f, 0.f, 0.f, 0.f);

#pragma unroll 8
    for (int k = 0; k < 64; k++) {
        float4 w = sW4[k * 16 + fg];
#pragma unroll
        for (int i = 0; i < 4; i++) {
            float hv = sh[(ns * 4 + i) * 65 + k];
            acc[i].x += hv * w.x;
            acc[i].y += hv * w.y;
            acc[i].z += hv * w.z;
            acc[i].w += hv * w.w;
        }
    }
#pragma unroll
    for (int i = 0; i < 4; i++) {
        int n = base + ns * 4 + i;
        if (n < NN) g_hw4[n * 16 + fg] = acc[i];
    }
}

// Pull aggregation, layer 2 + fused mean-pool accumulation
__global__ void k_agg2(const float* __restrict__ b) {
    int t = blockIdx.x * blockDim.x + threadIdx.x;
    if (t >= NN * 16) return;
    int n = t >> 4, c = t & 15;
    int row = __ldg(g_rowstart + n);
    int cnt = __ldg(g_indeg + n);
    float4 acc = make_float4(0.f, 0.f, 0.f, 0.f);
    for (int i = row; i < row + cnt; i++) {
        unsigned long long pk = __ldg(&g_csr[i]);
        int   s = (int)(unsigned)pk;
        float w = __uint_as_float((unsigned)(pk >> 32));
        float4 v = __ldg(&g_hw4[s * 16 + c]);
        acc.x += v.x * w; acc.y += v.y * w;
        acc.z += v.z * w; acc.w += v.w * w;
    }
    float di = g_dinv[n];
    float sl = di * di;
    float4 hw = g_hw4[t];
    float4 bb = __ldg((const float4*)b + c);
    float4 o;
    o.x = fmaxf(acc.x + hw.x * sl + bb.x, 0.f);
    o.y = fmaxf(acc.y + hw.y * sl + bb.y, 0.f);
    o.z = fmaxf(acc.z + hw.z * sl + bb.z, 0.f);
    o.w = fmaxf(acc.w + hw.w * sl + bb.w, 0.f);
    int g = __ldg(g_batch + n);
    red_add_v4(&g_sums4[g * 16 + c], o);
}

__global__ void k_out(float4* __restrict__ out) {
    int t = blockIdx.x * blockDim.x + threadIdx.x;
    if (t >= NG * 16) return;
    int g = t >> 4;
    float inv = 1.0f / fmaxf(g_counts[g], 1.0f);
    float4 s = g_sums4[t];
    out[t] = make_float4(s.x * inv, s.y * inv, s.z * inv, s.w * inv);
}

// ---------------- launch ----------------------------------------------------

extern "C" void kernel_launch(void* const* d_in, const int* in_sizes, int n_in,
                              void* d_out, int out_size) {
    // Resolve inputs by element count (robust to ordering and index dtype).
    const float* x     = nullptr;
    const float* W1    = nullptr;
    const float* b1    = nullptr;
    const float* W2    = nullptr;
    const float* b2    = nullptr;
    const void*  ei    = nullptr;
    const void*  batch = nullptr;

    for (int i = 0; i < n_in; i++) {
        int sz = in_sizes[i];
        const void* p = d_in[i];
        switch (sz) {
            case 300000:  x     = (const float*)p; break;
            case 192:     W1    = (const float*)p; break;
            case 4096:    W2    = (const float*)p; break;
            case 2000000:
            case 4000000: ei    = p; break;
            case 100000:
            case 200000:  batch = p; break;
            case 64:
                if (!b1) b1 = (const float*)p;
                else     b2 = (const float*)p;
                break;
            default: break;
        }
    }

    const int TB = 256;
    const int gN    = (NN + TB - 1) / TB;        // 391
    const int gE    = (NE + TB - 1) / TB;        // 3907
    const int gN16  = (NN * 16 + TB - 1) / TB;   // 6250
    const int gG    = (NG * 16 + TB - 1) / TB;   // 32
    const int gGemm = (NN + 63) / 64;            // 1563

    k_detect<<<1, 1>>>(ei);
    k_init<<<gN, TB>>>();
    k_cvt<<<gE, TB>>>(ei, batch);
    k_dinv<<<gN, TB>>>();

    // CSR build
    k_scan1<<<NBLK, 1024>>>();
    k_scan2<<<1, 1>>>();
    k_scan3<<<gN, TB>>>();
    k_place<<<gE, TB>>>();

    // layer 1
    k_xw1<<<gN16, TB>>>(x, W1);
    k_agg1<<<gN16, TB>>>(b1);

    // layer 2
    k_gemm<<<gGemm, TB>>>(W2);
    k_agg2<<<gN16, TB>>>(b2);

    k_out<<<gG, TB>>>((float4*)d_out);
}

// round 9
// speedup vs baseline: 2.0788x; 1.0089x over previous
#include <cuda_runtime.h>
#include <cuda_fp16.h>

#define NN 100000
#define NE 1000000
#define NG 512
#define HID 64
#define NBLK 98   // ceil(NN/1024)

// ---------------- scratch (static device globals; no allocation) ------------
__device__ int    g_is64;
__device__ int    g_batch[NN];
__device__ int    g_indeg[NN];
__device__ int    g_rowtmp[NN];
__device__ int    g_rowstart[NN];
__device__ int    g_cursor[NN];
__device__ int    g_blk[NBLK];
__device__ unsigned long long g_csr[NE];     // packed (norm<<32 | src)
__device__ float  g_dinv[NN];
__device__ unsigned long long g_hwh[NN * 16]; // fp16 feature copy, 4 halves/slot
__device__ float4 g_hw4[NN * 16];            // fp32 features (layer-2 self term)
__device__ float4 g_h4[NN * 16];             // layer-1 output (gemm input)
__device__ float4 g_sums4[NG * 16];
__device__ float  g_counts[NG];

__device__ __forceinline__ void red_add_v4(float4* a, float4 v) {
    asm volatile("red.global.add.v4.f32 [%0], {%1,%2,%3,%4};"
                 :: "l"(a), "f"(v.x), "f"(v.y), "f"(v.z), "f"(v.w)
                 : "memory");
}

__device__ __forceinline__ unsigned long long pack4h(float4 o) {
    __half2 ha = __floats2half2_rn(o.x, o.y);
    __half2 hb = __floats2half2_rn(o.z, o.w);
    unsigned ua = *reinterpret_cast<unsigned*>(&ha);
    unsigned ub = *reinterpret_cast<unsigned*>(&hb);
    return ((unsigned long long)ub << 32) | ua;
}

// ---------------- setup kernels ---------------------------------------------

// init + dtype detection (int64 ids all < NN; int32-as-int64 fails w.p. 1-1e-40)
__global__ void k_init(const void* ei_raw) {
    int i = blockIdx.x * blockDim.x + threadIdx.x;
    if (i == 0) {
        const long long* p = (const long long*)ei_raw;
        int ok = 1;
#pragma unroll
        for (int j = 0; j < 8; j++) {
            long long v = p[j];
            if (v < 0 || v >= NN) ok = 0;
        }
        g_is64 = ok;
    }
    if (i < NN)      g_indeg[i] = 0;
    if (i < NG * 16) g_sums4[i] = make_float4(0.f, 0.f, 0.f, 0.f);
    if (i < NG)      g_counts[i] = 0.0f;
}

// degree + batch conversion (no edge staging)
__global__ void k_cvt(const void* ei_raw, const void* batch_raw) {
    int i = blockIdx.x * blockDim.x + threadIdx.x;
    int is64 = g_is64;
    if (i < NE) {
        int d = is64 ? (int)((const long long*)ei_raw)[NE + i]
                     : ((const int*)ei_raw)[NE + i];
        atomicAdd(&g_indeg[d], 1);
    }
    if (i < NN) {
        int b = is64 ? (int)((const long long*)batch_raw)[i]
                     : ((const int*)batch_raw)[i];
        g_batch[i] = b;
        atomicAdd(&g_counts[b], 1.0f);
    }
}

// ---- exclusive scan of g_indeg -> g_rowstart --------------------------------

__global__ void k_scan1() {
    __shared__ int sh[1024];
    int n = blockIdx.x * 1024 + threadIdx.x;
    int v = (n < NN) ? g_indeg[n] : 0;
    sh[threadIdx.x] = v;
    __syncthreads();
#pragma unroll
    for (int off = 1; off < 1024; off <<= 1) {
        int cur = sh[threadIdx.x];
        int add = (threadIdx.x >= off) ? sh[threadIdx.x - off] : 0;
        __syncthreads();
        sh[threadIdx.x] = cur + add;
        __syncthreads();
    }
    if (n < NN) g_rowtmp[n] = sh[threadIdx.x] - v;
    if (threadIdx.x == 1023) g_blk[blockIdx.x] = sh[1023];
}

__global__ void k_scan2() {
    int acc = 0;
    for (int i = 0; i < NBLK; i++) { int v = g_blk[i]; g_blk[i] = acc; acc += v; }
}

// finalize rowstart/cursor + dinv
__global__ void k_scan3() {
    int n = blockIdx.x * blockDim.x + threadIdx.x;
    if (n < NN) {
        int row = g_rowtmp[n] + g_blk[n >> 10];
        g_rowstart[n] = row;
        g_cursor[n]   = row;
        g_dinv[n]     = rsqrtf((float)g_indeg[n] + 1.0f);  // +1 self loop
    }
}

// place edges into dst-ordered CSR with precomputed norm
__global__ void k_place(const void* ei_raw) {
    int e = blockIdx.x * blockDim.x + threadIdx.x;
    if (e >= NE) return;
    int s, d;
    if (g_is64) {
        const long long* p = (const long long*)ei_raw;
        s = (int)p[e]; d = (int)p[NE + e];
    } else {
        const int* p = (const int*)ei_raw;
        s = p[e]; d = p[NE + e];
    }
    float w = g_dinv[s] * g_dinv[d];
    int pos = atomicAdd(&g_cursor[d], 1);
    g_csr[pos] = ((unsigned long long)__float_as_uint(w) << 32) | (unsigned)s;
}

// ---------------- compute kernels -------------------------------------------

// hw = x @ W1, stored fp16 only (self term recomputed in agg1)
__global__ void k_xw1(const float* __restrict__ x, const float* __restrict__ W1) {
    int t = blockIdx.x * blockDim.x + threadIdx.x;
    if (t >= NN * 16) return;
    int n = t >> 4, c = t & 15;
    float x0 = __ldg(x + n * 3 + 0);
    float x1 = __ldg(x + n * 3 + 1);
    float x2 = __ldg(x + n * 3 + 2);
    float4 w0 = __ldg((const float4*)(W1)       + c);
    float4 w1 = __ldg((const float4*)(W1 + 64)  + c);
    float4 w2 = __ldg((const float4*)(W1 + 128) + c);
    float4 o;
    o.x = x0 * w0.x + x1 * w1.x + x2 * w2.x;
    o.y = x0 * w0.y + x1 * w1.y + x2 * w2.y;
    o.z = x0 * w0.z + x1 * w1.z + x2 * w2.z;
    o.w = x0 * w0.w + x1 * w1.w + x2 * w2.w;
    g_hwh[t] = pack4h(o);
}

// layer-1 pull aggregation (fp16 gathers, fp32 accum; self term recomputed fp32)
__global__ void k_agg1(const float* __restrict__ x, const float* __restrict__ W1,
                       const float* __restrict__ b) {
    int t = blockIdx.x * blockDim.x + threadIdx.x;
    if (t >= NN * 16) return;
    int n = t >> 4, c = t & 15;
    int row = __ldg(g_rowstart + n);
    int cnt = __ldg(g_indeg + n);
    float4 acc = make_float4(0.f, 0.f, 0.f, 0.f);
    for (int i = row; i < row + cnt; i++) {
        unsigned long long pk = __ldg(&g_csr[i]);
        int   s = (int)(unsigned)pk;
        float w = __uint_as_float((unsigned)(pk >> 32));
        unsigned long long fv = __ldg(&g_hwh[s * 16 + c]);
        unsigned lo = (unsigned)fv, hi = (unsigned)(fv >> 32);
        float2 f0 = __half22float2(*reinterpret_cast<__half2*>(&lo));
        float2 f1 = __half22float2(*reinterpret_cast<__half2*>(&hi));
        acc.x += f0.x * w; acc.y += f0.y * w;
        acc.z += f1.x * w; acc.w += f1.y * w;
    }
    // exact fp32 self term: (x@W1)[n,c] * dinv^2
    float x0 = __ldg(x + n * 3 + 0);
    float x1 = __ldg(x + n * 3 + 1);
    float x2 = __ldg(x + n * 3 + 2);
    float4 w0 = __ldg((const float4*)(W1)       + c);
    float4 w1 = __ldg((const float4*)(W1 + 64)  + c);
    float4 w2 = __ldg((const float4*)(W1 + 128) + c);
    float di = g_dinv[n];
    float sl = di * di;
    float4 bb = __ldg((const float4*)b + c);
    float4 o;
    o.x = fmaxf(acc.x + (x0*w0.x + x1*w1.x + x2*w2.x) * sl + bb.x, 0.f);
    o.y = fmaxf(acc.y + (x0*w0.y + x1*w1.y + x2*w2.y) * sl + bb.y, 0.f);
    o.z = fmaxf(acc.z + (x0*w0.z + x1*w1.z + x2*w2.z) * sl + bb.z, 0.f);
    o.w = fmaxf(acc.w + (x0*w0.w + x1*w1.w + x2*w2.w) * sl + bb.w, 0.f);
    g_h4[t] = o;
}

// hw = h @ W2; writes fp32 (self term) + fp16 (gather copy)
__global__ void k_gemm(const float* __restrict__ W2) {
    __shared__ float sW[64 * 64];
    __shared__ float sh[64 * 65];
    int t = threadIdx.x;
    int base = blockIdx.x * 64;

    float4* sW4 = (float4*)sW;
    const float4* W24 = (const float4*)W2;
    for (int i = t; i < 1024; i += 256) sW4[i] = __ldg(W24 + i);

    const float* hflat = (const float*)g_h4;
    for (int i = t; i < 4096; i += 256) {
        int nl = i >> 6, k = i & 63;
        int n = base + nl;
        sh[nl * 65 + k] = (n < NN) ? hflat[n * 64 + k] : 0.f;
    }
    __syncthreads();

    int fg = t & 15, ns = t >> 4;
    float4 acc[4];
#pragma unroll
    for (int i = 0; i < 4; i++) acc[i] = make_float4(0.f, 0.f, 0.f, 0.f);

#pragma unroll 8
    for (int k = 0; k < 64; k++) {
        float4 w = sW4[k * 16 + fg];
#pragma unroll
        for (int i = 0; i < 4; i++) {
            float hv = sh[(ns * 4 + i) * 65 + k];
            acc[i].x += hv * w.x;
            acc[i].y += hv * w.y;
            acc[i].z += hv * w.z;
            acc[i].w += hv * w.w;
        }
    }
#pragma unroll
    for (int i = 0; i < 4; i++) {
        int n = base + ns * 4 + i;
        if (n < NN) {
            g_hw4[n * 16 + fg] = acc[i];
            g_hwh[n * 16 + fg] = pack4h(acc[i]);
        }
    }
}

// layer-2 pull aggregation + fused mean-pool accumulation
__global__ void k_agg2(const float* __restrict__ b) {
    int t = blockIdx.x * blockDim.x + threadIdx.x;
    if (t >= NN * 16) return;
    int n = t >> 4, c = t & 15;
    int row = __ldg(g_rowstart + n);
    int cnt = __ldg(g_indeg + n);
    float4 acc = make_float4(0.f, 0.f, 0.f, 0.f);
    for (int i = row; i < row + cnt; i++) {
        unsigned long long pk = __ldg(&g_csr[i]);
        int   s = (int)(unsigned)pk;
        float w = __uint_as_float((unsigned)(pk >> 32));
        unsigned long long fv = __ldg(&g_hwh[s * 16 + c]);
        unsigned lo = (unsigned)fv, hi = (unsigned)(fv >> 32);
        float2 f0 = __half22float2(*reinterpret_cast<__half2*>(&lo));
        float2 f1 = __half22float2(*reinterpret_cast<__half2*>(&hi));
        acc.x += f0.x * w; acc.y += f0.y * w;
        acc.z += f1.x * w; acc.w += f1.y * w;
    }
    float di = g_dinv[n];
    float sl = di * di;
    float4 hw = g_hw4[t];
    float4 bb = __ldg((const float4*)b + c);
    float4 o;
    o.x = fmaxf(acc.x + hw.x * sl + bb.x, 0.f);
    o.y = fmaxf(acc.y + hw.y * sl + bb.y, 0.f);
    o.z = fmaxf(acc.z + hw.z * sl + bb.z, 0.f);
    o.w = fmaxf(acc.w + hw.w * sl + bb.w, 0.f);
    int g = __ldg(g_batch + n);
    red_add_v4(&g_sums4[g * 16 + c], o);
}

__global__ void k_out(float4* __restrict__ out) {
    int t = blockIdx.x * blockDim.x + threadIdx.x;
    if (t >= NG * 16) return;
    int g = t >> 4;
    float inv = 1.0f / fmaxf(g_counts[g], 1.0f);
    float4 s = g_sums4[t];
    out[t] = make_float4(s.x * inv, s.y * inv, s.z * inv, s.w * inv);
}

// ---------------- launch ----------------------------------------------------

extern "C" void kernel_launch(void* const* d_in, const int* in_sizes, int n_in,
                              void* d_out, int out_size) {
    const float* x     = nullptr;
    const float* W1    = nullptr;
    const float* b1    = nullptr;
    const float* W2    = nullptr;
    const float* b2    = nullptr;
    const void*  ei    = nullptr;
    const void*  batch = nullptr;

    for (int i = 0; i < n_in; i++) {
        int sz = in_sizes[i];
        const void* p = d_in[i];
        switch (sz) {
            case 300000:  x     = (const float*)p; break;
            case 192:     W1    = (const float*)p; break;
            case 4096:    W2    = (const float*)p; break;
            case 2000000:
            case 4000000: ei    = p; break;
            case 100000:
            case 200000:  batch = p; break;
            case 64:
                if (!b1) b1 = (const float*)p;
                else     b2 = (const float*)p;
                break;
            default: break;
        }
    }

    const int TB = 256;
    const int gN    = (NN + TB - 1) / TB;        // 391
    const int gE    = (NE + TB - 1) / TB;        // 3907
    const int gN16  = (NN * 16 + TB - 1) / TB;   // 6250
    const int gG    = (NG * 16 + TB - 1) / TB;   // 32
    const int gGemm = (NN + 63) / 64;            // 1563

    k_init<<<gN, TB>>>(ei);
    k_cvt<<<gE, TB>>>(ei, batch);
    k_scan1<<<NBLK, 1024>>>();
    k_scan2<<<1, 1>>>();
    k_scan3<<<gN, TB>>>();
    k_place<<<gE, TB>>>(ei);

    k_xw1<<<gN16, TB>>>(x, W1);
    k_agg1<<<gN16, TB>>>(x, W1, b1);

    k_gemm<<<gGemm, TB>>>(W2);
    k_agg2<<<gN16, TB>>>(b2);

    k_out<<<gG, TB>>>((float4*)d_out);
}

// round 10
// speedup vs baseline: 2.1125x; 1.0162x over previous
#include <cuda_runtime.h>
#include <cuda_fp16.h>

#define NN 100000
#define NE 1000000
#define NG 512
#define HID 64
#define NBLK 98   // ceil(NN/1024)

// ---------------- scratch (static device globals; no allocation) ------------
__device__ int    g_is64;
__device__ int    g_batch[NN];
__device__ int    g_indeg[NN];
__device__ int    g_rowtmp[NN];
__device__ int    g_rowstart[NN];
__device__ int    g_cursor[NN];
__device__ int    g_blk[NBLK];
__device__ unsigned long long g_csr[NE];      // packed (norm<<32 | src)
__device__ float  g_dinv[NN];
__device__ unsigned long long g_hwh[NN * 16]; // fp16 feature copy, 4 halves/slot
__device__ float4 g_hw4[NN * 16];             // fp32 features (layer-2 self term)
__device__ float4 g_h4[NN * 16];              // layer-1 output (gemm input)
__device__ float4 g_sums4[NG * 16];
__device__ float  g_counts[NG];

__device__ __forceinline__ void red_add_v4(float4* a, float4 v) {
    asm volatile("red.global.add.v4.f32 [%0], {%1,%2,%3,%4};"
                 :: "l"(a), "f"(v.x), "f"(v.y), "f"(v.z), "f"(v.w)
                 : "memory");
}

__device__ __forceinline__ unsigned long long pack4h(float4 o) {
    __half2 ha = __floats2half2_rn(o.x, o.y);
    __half2 hb = __floats2half2_rn(o.z, o.w);
    unsigned ua = *reinterpret_cast<unsigned*>(&ha);
    unsigned ub = *reinterpret_cast<unsigned*>(&hb);
    return ((unsigned long long)ub << 32) | ua;
}

__device__ __forceinline__ void acc_edge(float4& acc, unsigned long long pk,
                                         unsigned long long fv) {
    float w = __uint_as_float((unsigned)(pk >> 32));
    unsigned lo = (unsigned)fv, hi = (unsigned)(fv >> 32);
    float2 f0 = __half22float2(*reinterpret_cast<__half2*>(&lo));
    float2 f1 = __half22float2(*reinterpret_cast<__half2*>(&hi));
    acc.x += f0.x * w; acc.y += f0.y * w;
    acc.z += f1.x * w; acc.w += f1.y * w;
}

// 4-deep software-pipelined CSR aggregation for (node n, chunk c)
__device__ __forceinline__ float4 agg_node(int n, int c) {
    int e   = __ldg(g_rowstart + n);
    int end = e + __ldg(g_indeg + n);
    float4 acc = make_float4(0.f, 0.f, 0.f, 0.f);
    for (; e + 4 <= end; e += 4) {
        unsigned long long pk0 = __ldg(&g_csr[e + 0]);
        unsigned long long pk1 = __ldg(&g_csr[e + 1]);
        unsigned long long pk2 = __ldg(&g_csr[e + 2]);
        unsigned long long pk3 = __ldg(&g_csr[e + 3]);
        unsigned long long f0 = __ldg(&g_hwh[((int)(unsigned)pk0) * 16 + c]);
        unsigned long long f1 = __ldg(&g_hwh[((int)(unsigned)pk1) * 16 + c]);
        unsigned long long f2 = __ldg(&g_hwh[((int)(unsigned)pk2) * 16 + c]);
        unsigned long long f3 = __ldg(&g_hwh[((int)(unsigned)pk3) * 16 + c]);
        acc_edge(acc, pk0, f0);
        acc_edge(acc, pk1, f1);
        acc_edge(acc, pk2, f2);
        acc_edge(acc, pk3, f3);
    }
    for (; e < end; e++) {
        unsigned long long pk = __ldg(&g_csr[e]);
        unsigned long long fv = __ldg(&g_hwh[((int)(unsigned)pk) * 16 + c]);
        acc_edge(acc, pk, fv);
    }
    return acc;
}

// ---------------- setup kernels ---------------------------------------------

// init + dtype detection (int64 ids all < NN; int32-as-int64 fails w.p. 1-1e-40)
__global__ void k_init(const void* ei_raw) {
    int i = blockIdx.x * blockDim.x + threadIdx.x;
    if (i == 0) {
        const long long* p = (const long long*)ei_raw;
        int ok = 1;
#pragma unroll
        for (int j = 0; j < 8; j++) {
            long long v = p[j];
            if (v < 0 || v >= NN) ok = 0;
        }
        g_is64 = ok;
    }
    if (i < NN)      g_indeg[i] = 0;
    if (i < NG * 16) g_sums4[i] = make_float4(0.f, 0.f, 0.f, 0.f);
    if (i < NG)      g_counts[i] = 0.0f;
}

// degree + batch conversion
__global__ void k_cvt(const void* ei_raw, const void* batch_raw) {
    int i = blockIdx.x * blockDim.x + threadIdx.x;
    int is64 = g_is64;
    if (i < NE) {
        int d = is64 ? (int)((const long long*)ei_raw)[NE + i]
                     : ((const int*)ei_raw)[NE + i];
        atomicAdd(&g_indeg[d], 1);
    }
    if (i < NN) {
        int b = is64 ? (int)((const long long*)batch_raw)[i]
                     : ((const int*)batch_raw)[i];
        g_batch[i] = b;
        atomicAdd(&g_counts[b], 1.0f);
    }
}

// ---- exclusive scan of g_indeg -> g_rowstart --------------------------------

__global__ void k_scan1() {
    __shared__ int sh[1024];
    int n = blockIdx.x * 1024 + threadIdx.x;
    int v = (n < NN) ? g_indeg[n] : 0;
    sh[threadIdx.x] = v;
    __syncthreads();
#pragma unroll
    for (int off = 1; off < 1024; off <<= 1) {
        int cur = sh[threadIdx.x];
        int add = (threadIdx.x >= off) ? sh[threadIdx.x - off] : 0;
        __syncthreads();
        sh[threadIdx.x] = cur + add;
        __syncthreads();
    }
    if (n < NN) g_rowtmp[n] = sh[threadIdx.x] - v;
    if (threadIdx.x == 1023) g_blk[blockIdx.x] = sh[1023];
}

// parallel 128-wide scan of the 98 block sums (was 7.6us single-threaded)
__global__ void k_scan2() {
    __shared__ int sh[128];
    int i = threadIdx.x;
    int v = (i < NBLK) ? g_blk[i] : 0;
    sh[i] = v;
    __syncthreads();
#pragma unroll
    for (int off = 1; off < 128; off <<= 1) {
        int cur = sh[i];
        int add = (i >= off) ? sh[i - off] : 0;
        __syncthreads();
        sh[i] = cur + add;
        __syncthreads();
    }
    if (i < NBLK) g_blk[i] = sh[i] - v;   // exclusive
}

// finalize rowstart/cursor + dinv
__global__ void k_scan3() {
    int n = blockIdx.x * blockDim.x + threadIdx.x;
    if (n < NN) {
        int row = g_rowtmp[n] + g_blk[n >> 10];
        g_rowstart[n] = row;
        g_cursor[n]   = row;
        g_dinv[n]     = rsqrtf((float)g_indeg[n] + 1.0f);  // +1 self loop
    }
}

// place edges into dst-ordered CSR with precomputed norm
__global__ void k_place(const void* ei_raw) {
    int e = blockIdx.x * blockDim.x + threadIdx.x;
    if (e >= NE) return;
    int s, d;
    if (g_is64) {
        const long long* p = (const long long*)ei_raw;
        s = (int)p[e]; d = (int)p[NE + e];
    } else {
        const int* p = (const int*)ei_raw;
        s = p[e]; d = p[NE + e];
    }
    float w = g_dinv[s] * g_dinv[d];
    int pos = atomicAdd(&g_cursor[d], 1);
    g_csr[pos] = ((unsigned long long)__float_as_uint(w) << 32) | (unsigned)s;
}

// ---------------- compute kernels -------------------------------------------

// hw = x @ W1, stored fp16 only (self term recomputed in agg1)
__global__ void k_xw1(const float* __restrict__ x, const float* __restrict__ W1) {
    int t = blockIdx.x * blockDim.x + threadIdx.x;
    if (t >= NN * 16) return;
    int n = t >> 4, c = t & 15;
    float x0 = __ldg(x + n * 3 + 0);
    float x1 = __ldg(x + n * 3 + 1);
    float x2 = __ldg(x + n * 3 + 2);
    float4 w0 = __ldg((const float4*)(W1)       + c);
    float4 w1 = __ldg((const float4*)(W1 + 64)  + c);
    float4 w2 = __ldg((const float4*)(W1 + 128) + c);
    float4 o;
    o.x = x0 * w0.x + x1 * w1.x + x2 * w2.x;
    o.y = x0 * w0.y + x1 * w1.y + x2 * w2.y;
    o.z = x0 * w0.z + x1 * w1.z + x2 * w2.z;
    o.w = x0 * w0.w + x1 * w1.w + x2 * w2.w;
    g_hwh[t] = pack4h(o);
}

// layer-1 pull aggregation (fp16 gathers, fp32 accum; self term recomputed fp32)
__global__ void k_agg1(const float* __restrict__ x, const float* __restrict__ W1,
                       const float* __restrict__ b) {
    int t = blockIdx.x * blockDim.x + threadIdx.x;
    if (t >= NN * 16) return;
    int n = t >> 4, c = t & 15;
    float4 acc = agg_node(n, c);
    float x0 = __ldg(x + n * 3 + 0);
    float x1 = __ldg(x + n * 3 + 1);
    float x2 = __ldg(x + n * 3 + 2);
    float4 w0 = __ldg((const float4*)(W1)       + c);
    float4 w1 = __ldg((const float4*)(W1 + 64)  + c);
    float4 w2 = __ldg((const float4*)(W1 + 128) + c);
    float di = g_dinv[n];
    float sl = di * di;
    float4 bb = __ldg((const float4*)b + c);
    float4 o;
    o.x = fmaxf(acc.x + (x0*w0.x + x1*w1.x + x2*w2.x) * sl + bb.x, 0.f);
    o.y = fmaxf(acc.y + (x0*w0.y + x1*w1.y + x2*w2.y) * sl + bb.y, 0.f);
    o.z = fmaxf(acc.z + (x0*w0.z + x1*w1.z + x2*w2.z) * sl + bb.z, 0.f);
    o.w = fmaxf(acc.w + (x0*w0.w + x1*w1.w + x2*w2.w) * sl + bb.w, 0.f);
    g_h4[t] = o;
}

// hw = h @ W2; writes fp32 (self term) + fp16 (gather copy)
__global__ void k_gemm(const float* __restrict__ W2) {
    __shared__ float sW[64 * 64];
    __shared__ float sh[64 * 65];
    int t = threadIdx.x;
    int base = blockIdx.x * 64;

    float4* sW4 = (float4*)sW;
    const float4* W24 = (const float4*)W2;
    for (int i = t; i < 1024; i += 256) sW4[i] = __ldg(W24 + i);

    const float* hflat = (const float*)g_h4;
    for (int i = t; i < 4096; i += 256) {
        int nl = i >> 6, k = i & 63;
        int n = base + nl;
        sh[nl * 65 + k] = (n < NN) ? hflat[n * 64 + k] : 0.f;
    }
    __syncthreads();

    int fg = t & 15, ns = t >> 4;
    float4 acc[4];
#pragma unroll
    for (int i = 0; i < 4; i++) acc[i] = make_float4(0.f, 0.f, 0.f, 0.f);

#pragma unroll 8
    for (int k = 0; k < 64; k++) {
        float4 w = sW4[k * 16 + fg];
#pragma unroll
        for (int i = 0; i < 4; i++) {
            float hv = sh[(ns * 4 + i) * 65 + k];
            acc[i].x += hv * w.x;
            acc[i].y += hv * w.y;
            acc[i].z += hv * w.z;
            acc[i].w += hv * w.w;
        }
    }
#pragma unroll
    for (int i = 0; i < 4; i++) {
        int n = base + ns * 4 + i;
        if (n < NN) {
            g_hw4[n * 16 + fg] = acc[i];
            g_hwh[n * 16 + fg] = pack4h(acc[i]);
        }
    }
}

// layer-2 pull aggregation + fused mean-pool accumulation
__global__ void k_agg2(const float* __restrict__ b) {
    int t = blockIdx.x * blockDim.x + threadIdx.x;
    if (t >= NN * 16) return;
    int n = t >> 4, c = t & 15;
    float4 acc = agg_node(n, c);
    float di = g_dinv[n];
    float sl = di * di;
    float4 hw = g_hw4[t];
    float4 bb = __ldg((const float4*)b + c);
    float4 o;
    o.x = fmaxf(acc.x + hw.x * sl + bb.x, 0.f);
    o.y = fmaxf(acc.y + hw.y * sl + bb.y, 0.f);
    o.z = fmaxf(acc.z + hw.z * sl + bb.z, 0.f);
    o.w = fmaxf(acc.w + hw.w * sl + bb.w, 0.f);
    int g = __ldg(g_batch + n);
    red_add_v4(&g_sums4[g * 16 + c], o);
}

__global__ void k_out(float4* __restrict__ out) {
    int t = blockIdx.x * blockDim.x + threadIdx.x;
    if (t >= NG * 16) return;
    int g = t >> 4;
    float inv = 1.0f / fmaxf(g_counts[g], 1.0f);
    float4 s = g_sums4[t];
    out[t] = make_float4(s.x * inv, s.y * inv, s.z * inv, s.w * inv);
}

// ---------------- launch ----------------------------------------------------

extern "C" void kernel_launch(void* const* d_in, const int* in_sizes, int n_in,
                              void* d_out, int out_size) {
    const float* x     = nullptr;
    const float* W1    = nullptr;
    const float* b1    = nullptr;
    const float* W2    = nullptr;
    const float* b2    = nullptr;
    const void*  ei    = nullptr;
    const void*  batch = nullptr;

    for (int i = 0; i < n_in; i++) {
        int sz = in_sizes[i];
        const void* p = d_in[i];
        switch (sz) {
            case 300000:  x     = (const float*)p; break;
            case 192:     W1    = (const float*)p; break;
            case 4096:    W2    = (const float*)p; break;
            case 2000000:
            case 4000000: ei    = p; break;
            case 100000:
            case 200000:  batch = p; break;
            case 64:
                if (!b1) b1 = (const float*)p;
                else     b2 = (const float*)p;
                break;
            default: break;
        }
    }

    const int TB = 256;
    const int gN    = (NN + TB - 1) / TB;        // 391
    const int gE    = (NE + TB - 1) / TB;        // 3907
    const int gN16  = (NN * 16 + TB - 1) / TB;   // 6250
    const int gG    = (NG * 16 + TB - 1) / TB;   // 32
    const int gGemm = (NN + 63) / 64;            // 1563

    k_init<<<gN, TB>>>(ei);
    k_cvt<<<gE, TB>>>(ei, batch);
    k_scan1<<<NBLK, 1024>>>();
    k_scan2<<<1, 128>>>();
    k_scan3<<<gN, TB>>>();
    k_place<<<gE, TB>>>(ei);

    k_xw1<<<gN16, TB>>>(x, W1);
    k_agg1<<<gN16, TB>>>(x, W1, b1);

    k_gemm<<<gGemm, TB>>>(W2);
    k_agg2<<<gN16, TB>>>(b2);

    k_out<<<gG, TB>>>((float4*)d_out);
}

// round 11
// speedup vs baseline: 2.4663x; 1.1675x over previous
#include <cuda_runtime.h>
#include <cuda_fp16.h>

#define NN 100000
#define NE 1000000
#define NG 512
#define HID 64
#define NBLK 98   // ceil(NN/1024)

// ---------------- scratch (static device globals; no allocation) ------------
__device__ int    g_is64;
__device__ int    g_batch[NN];
__device__ int    g_indeg[NN];
__device__ int    g_rowtmp[NN];
__device__ int    g_rowstart[NN];
__device__ int    g_cursor[NN];
__device__ int    g_blk[NBLK];
__device__ unsigned long long g_csr[NE];      // packed (norm<<32 | src)
__device__ float  g_dinv[NN];
__device__ unsigned long long g_hh[NN * 16];  // h (layer-1 out), fp16 x4 per slot
__device__ unsigned long long g_m[NN * 16];   // agg(h)+self, fp16 x4 per slot
__device__ float4 g_sums4[NG * 16];
__device__ float  g_counts[NG];

__device__ __forceinline__ void red_add_v4(float4* a, float4 v) {
    asm volatile("red.global.add.v4.f32 [%0], {%1,%2,%3,%4};"
                 :: "l"(a), "f"(v.x), "f"(v.y), "f"(v.z), "f"(v.w)
                 : "memory");
}

__device__ __forceinline__ unsigned long long pack4h(float4 o) {
    __half2 ha = __floats2half2_rn(o.x, o.y);
    __half2 hb = __floats2half2_rn(o.z, o.w);
    unsigned ua = *reinterpret_cast<unsigned*>(&ha);
    unsigned ub = *reinterpret_cast<unsigned*>(&hb);
    return ((unsigned long long)ub << 32) | ua;
}

__device__ __forceinline__ float4 unpack4h(unsigned long long fv) {
    unsigned lo = (unsigned)fv, hi = (unsigned)(fv >> 32);
    float2 f0 = __half22float2(*reinterpret_cast<__half2*>(&lo));
    float2 f1 = __half22float2(*reinterpret_cast<__half2*>(&hi));
    return make_float4(f0.x, f0.y, f1.x, f1.y);
}

__device__ __forceinline__ void acc_edge(float4& acc, unsigned long long pk,
                                         unsigned long long fv) {
    float w = __uint_as_float((unsigned)(pk >> 32));
    float4 f = unpack4h(fv);
    acc.x += f.x * w; acc.y += f.y * w;
    acc.z += f.z * w; acc.w += f.w * w;
}

// ---------------- setup kernels ---------------------------------------------

__global__ void k_init(const void* ei_raw) {
    int i = blockIdx.x * blockDim.x + threadIdx.x;
    if (i == 0) {
        const long long* p = (const long long*)ei_raw;
        int ok = 1;
#pragma unroll
        for (int j = 0; j < 8; j++) {
            long long v = p[j];
            if (v < 0 || v >= NN) ok = 0;
        }
        g_is64 = ok;
    }
    if (i < NN)      g_indeg[i] = 0;
    if (i < NG * 16) g_sums4[i] = make_float4(0.f, 0.f, 0.f, 0.f);
    if (i < NG)      g_counts[i] = 0.0f;
}

__global__ void k_cvt(const void* ei_raw, const void* batch_raw) {
    int i = blockIdx.x * blockDim.x + threadIdx.x;
    int is64 = g_is64;
    if (i < NE) {
        int d = is64 ? (int)((const long long*)ei_raw)[NE + i]
                     : ((const int*)ei_raw)[NE + i];
        atomicAdd(&g_indeg[d], 1);
    }
    if (i < NN) {
        int b = is64 ? (int)((const long long*)batch_raw)[i]
                     : ((const int*)batch_raw)[i];
        g_batch[i] = b;
        atomicAdd(&g_counts[b], 1.0f);
    }
}

__global__ void k_scan1() {
    __shared__ int sh[1024];
    int n = blockIdx.x * 1024 + threadIdx.x;
    int v = (n < NN) ? g_indeg[n] : 0;
    sh[threadIdx.x] = v;
    __syncthreads();
#pragma unroll
    for (int off = 1; off < 1024; off <<= 1) {
        int cur = sh[threadIdx.x];
        int add = (threadIdx.x >= off) ? sh[threadIdx.x - off] : 0;
        __syncthreads();
        sh[threadIdx.x] = cur + add;
        __syncthreads();
    }
    if (n < NN) g_rowtmp[n] = sh[threadIdx.x] - v;
    if (threadIdx.x == 1023) g_blk[blockIdx.x] = sh[1023];
}

__global__ void k_scan2() {
    __shared__ int sh[128];
    int i = threadIdx.x;
    int v = (i < NBLK) ? g_blk[i] : 0;
    sh[i] = v;
    __syncthreads();
#pragma unroll
    for (int off = 1; off < 128; off <<= 1) {
        int cur = sh[i];
        int add = (i >= off) ? sh[i - off] : 0;
        __syncthreads();
        sh[i] = cur + add;
        __syncthreads();
    }
    if (i < NBLK) g_blk[i] = sh[i] - v;   // exclusive
}

__global__ void k_scan3() {
    int n = blockIdx.x * blockDim.x + threadIdx.x;
    if (n < NN) {
        int row = g_rowtmp[n] + g_blk[n >> 10];
        g_rowstart[n] = row;
        g_cursor[n]   = row;
        g_dinv[n]     = rsqrtf((float)g_indeg[n] + 1.0f);  // +1 self loop
    }
}

__global__ void k_place(const void* ei_raw) {
    int e = blockIdx.x * blockDim.x + threadIdx.x;
    if (e >= NE) return;
    int s, d;
    if (g_is64) {
        const long long* p = (const long long*)ei_raw;
        s = (int)p[e]; d = (int)p[NE + e];
    } else {
        const int* p = (const int*)ei_raw;
        s = p[e]; d = p[NE + e];
    }
    float w = g_dinv[s] * g_dinv[d];
    int pos = atomicAdd(&g_cursor[d], 1);
    g_csr[pos] = ((unsigned long long)__float_as_uint(w) << 32) | (unsigned)s;
}

// ---------------- compute kernels -------------------------------------------

// Layer 1, thread-per-node: aggregate raw x (3-dim) over in-edges, add self,
// then apply W1 + b1 + ReLU; store h as fp16.
__global__ void k_l1(const float* __restrict__ x, const float* __restrict__ W1,
                     const float* __restrict__ b1) {
    __shared__ float sW[192];
    __shared__ float sb[64];
    int t = threadIdx.x;
    if (t < 192) sW[t] = __ldg(W1 + t);
    if (t < 64)  sb[t] = __ldg(b1 + t);
    __syncthreads();

    int n = blockIdx.x * blockDim.x + t;
    if (n >= NN) return;

    int e   = __ldg(g_rowstart + n);
    int end = e + __ldg(g_indeg + n);
    float a0 = 0.f, a1 = 0.f, a2 = 0.f;
    for (; e + 4 <= end; e += 4) {
        unsigned long long pk0 = __ldg(&g_csr[e + 0]);
        unsigned long long pk1 = __ldg(&g_csr[e + 1]);
        unsigned long long pk2 = __ldg(&g_csr[e + 2]);
        unsigned long long pk3 = __ldg(&g_csr[e + 3]);
        int s0 = (int)(unsigned)pk0, s1 = (int)(unsigned)pk1;
        int s2 = (int)(unsigned)pk2, s3 = (int)(unsigned)pk3;
        float w0 = __uint_as_float((unsigned)(pk0 >> 32));
        float w1 = __uint_as_float((unsigned)(pk1 >> 32));
        float w2 = __uint_as_float((unsigned)(pk2 >> 32));
        float w3 = __uint_as_float((unsigned)(pk3 >> 32));
        float p00 = __ldg(x + s0*3), p01 = __ldg(x + s0*3+1), p02 = __ldg(x + s0*3+2);
        float p10 = __ldg(x + s1*3), p11 = __ldg(x + s1*3+1), p12 = __ldg(x + s1*3+2);
        float p20 = __ldg(x + s2*3), p21 = __ldg(x + s2*3+1), p22 = __ldg(x + s2*3+2);
        float p30 = __ldg(x + s3*3), p31 = __ldg(x + s3*3+1), p32 = __ldg(x + s3*3+2);
        a0 += w0*p00 + w1*p10 + w2*p20 + w3*p30;
        a1 += w0*p01 + w1*p11 + w2*p21 + w3*p31;
        a2 += w0*p02 + w1*p12 + w2*p22 + w3*p32;
    }
    for (; e < end; e++) {
        unsigned long long pk = __ldg(&g_csr[e]);
        int s = (int)(unsigned)pk;
        float w = __uint_as_float((unsigned)(pk >> 32));
        a0 += w * __ldg(x + s*3);
        a1 += w * __ldg(x + s*3+1);
        a2 += w * __ldg(x + s*3+2);
    }
    // self term
    float di = g_dinv[n];
    float sl = di * di;
    a0 += sl * __ldg(x + n*3);
    a1 += sl * __ldg(x + n*3+1);
    a2 += sl * __ldg(x + n*3+2);

    // h = relu([a0,a1,a2] @ W1 + b1), 4 outputs at a time
#pragma unroll
    for (int c = 0; c < 16; c++) {
        float4 o;
        o.x = fmaxf(a0*sW[c*4+0] + a1*sW[64+c*4+0] + a2*sW[128+c*4+0] + sb[c*4+0], 0.f);
        o.y = fmaxf(a0*sW[c*4+1] + a1*sW[64+c*4+1] + a2*sW[128+c*4+1] + sb[c*4+1], 0.f);
        o.z = fmaxf(a0*sW[c*4+2] + a1*sW[64+c*4+2] + a2*sW[128+c*4+2] + sb[c*4+2], 0.f);
        o.w = fmaxf(a0*sW[c*4+3] + a1*sW[64+c*4+3] + a2*sW[128+c*4+3] + sb[c*4+3], 0.f);
        g_hh[n * 16 + c] = pack4h(o);
    }
}

// Layer 2 aggregation: m = agg(h) + h*dinv^2, fp16 in / fp16 out
__global__ void k_aggh() {
    int t = blockIdx.x * blockDim.x + threadIdx.x;
    if (t >= NN * 16) return;
    int n = t >> 4, c = t & 15;
    int e   = __ldg(g_rowstart + n);
    int end = e + __ldg(g_indeg + n);
    float4 acc = make_float4(0.f, 0.f, 0.f, 0.f);
    for (; e + 4 <= end; e += 4) {
        unsigned long long pk0 = __ldg(&g_csr[e + 0]);
        unsigned long long pk1 = __ldg(&g_csr[e + 1]);
        unsigned long long pk2 = __ldg(&g_csr[e + 2]);
        unsigned long long pk3 = __ldg(&g_csr[e + 3]);
        unsigned long long f0 = __ldg(&g_hh[((int)(unsigned)pk0) * 16 + c]);
        unsigned long long f1 = __ldg(&g_hh[((int)(unsigned)pk1) * 16 + c]);
        unsigned long long f2 = __ldg(&g_hh[((int)(unsigned)pk2) * 16 + c]);
        unsigned long long f3 = __ldg(&g_hh[((int)(unsigned)pk3) * 16 + c]);
        acc_edge(acc, pk0, f0);
        acc_edge(acc, pk1, f1);
        acc_edge(acc, pk2, f2);
        acc_edge(acc, pk3, f3);
    }
    for (; e < end; e++) {
        unsigned long long pk = __ldg(&g_csr[e]);
        unsigned long long fv = __ldg(&g_hh[((int)(unsigned)pk) * 16 + c]);
        acc_edge(acc, pk, fv);
    }
    float di = g_dinv[n];
    float sl = di * di;
    float4 self = unpack4h(__ldg(&g_hh[t]));
    acc.x += self.x * sl; acc.y += self.y * sl;
    acc.z += self.z * sl; acc.w += self.w * sl;
    g_m[t] = pack4h(acc);
}

// out-row = relu(m @ W2 + b2); fused mean-pool accumulation. 64 nodes/block.
__global__ void k_gemm2(const float* __restrict__ W2, const float* __restrict__ b2) {
    __shared__ float sW[64 * 64];
    __shared__ float sh[64 * 65];
    int t = threadIdx.x;
    int base = blockIdx.x * 64;

    float4* sW4 = (float4*)sW;
    const float4* W24 = (const float4*)W2;
    for (int i = t; i < 1024; i += 256) sW4[i] = __ldg(W24 + i);

    for (int i = t; i < 64 * 16; i += 256) {
        int nl = i >> 4, c = i & 15;
        int n = base + nl;
        float4 v = (n < NN) ? unpack4h(__ldg(&g_m[n * 16 + c]))
                            : make_float4(0.f, 0.f, 0.f, 0.f);
        sh[nl * 65 + c * 4 + 0] = v.x;
        sh[nl * 65 + c * 4 + 1] = v.y;
        sh[nl * 65 + c * 4 + 2] = v.z;
        sh[nl * 65 + c * 4 + 3] = v.w;
    }
    __syncthreads();

    int fg = t & 15, ns = t >> 4;
    float4 acc[4];
#pragma unroll
    for (int i = 0; i < 4; i++) acc[i] = make_float4(0.f, 0.f, 0.f, 0.f);

#pragma unroll 8
    for (int k = 0; k < 64; k++) {
        float4 w = sW4[k * 16 + fg];
#pragma unroll
        for (int i = 0; i < 4; i++) {
            float hv = sh[(ns * 4 + i) * 65 + k];
            acc[i].x += hv * w.x;
            acc[i].y += hv * w.y;
            acc[i].z += hv * w.z;
            acc[i].w += hv * w.w;
        }
    }

    float4 bb = __ldg((const float4*)b2 + fg);
#pragma unroll
    for (int i = 0; i < 4; i++) {
        int n = base + ns * 4 + i;
        if (n < NN) {
            float4 o;
            o.x = fmaxf(acc[i].x + bb.x, 0.f);
            o.y = fmaxf(acc[i].y + bb.y, 0.f);
            o.z = fmaxf(acc[i].z + bb.z, 0.f);
            o.w = fmaxf(acc[i].w + bb.w, 0.f);
            int g = __ldg(g_batch + n);
            red_add_v4(&g_sums4[g * 16 + fg], o);
        }
    }
}

__global__ void k_out(float4* __restrict__ out) {
    int t = blockIdx.x * blockDim.x + threadIdx.x;
    if (t >= NG * 16) return;
    int g = t >> 4;
    float inv = 1.0f / fmaxf(g_counts[g], 1.0f);
    float4 s = g_sums4[t];
    out[t] = make_float4(s.x * inv, s.y * inv, s.z * inv, s.w * inv);
}

// ---------------- launch ----------------------------------------------------

extern "C" void kernel_launch(void* const* d_in, const int* in_sizes, int n_in,
                              void* d_out, int out_size) {
    const float* x     = nullptr;
    const float* W1    = nullptr;
    const float* b1    = nullptr;
    const float* W2    = nullptr;
    const float* b2    = nullptr;
    const void*  ei    = nullptr;
    const void*  batch = nullptr;

    for (int i = 0; i < n_in; i++) {
        int sz = in_sizes[i];
        const void* p = d_in[i];
        switch (sz) {
            case 300000:  x     = (const float*)p; break;
            case 192:     W1    = (const float*)p; break;
            case 4096:    W2    = (const float*)p; break;
            case 2000000:
            case 4000000: ei    = p; break;
            case 100000:
            case 200000:  batch = p; break;
            case 64:
                if (!b1) b1 = (const float*)p;
                else     b2 = (const float*)p;
                break;
            default: break;
        }
    }

    const int TB = 256;
    const int gN    = (NN + TB - 1) / TB;        // 391
    const int gE    = (NE + TB - 1) / TB;        // 3907
    const int gN16  = (NN * 16 + TB - 1) / TB;   // 6250
    const int gG    = (NG * 16 + TB - 1) / TB;   // 32
    const int gGemm = (NN + 63) / 64;            // 1563

    k_init<<<gN, TB>>>(ei);
    k_cvt<<<gE, TB>>>(ei, batch);
    k_scan1<<<NBLK, 1024>>>();
    k_scan2<<<1, 128>>>();
    k_scan3<<<gN, TB>>>();
    k_place<<<gE, TB>>>(ei);

    k_l1<<<gN, TB>>>(x, W1, b1);      // layer 1: 3-dim agg + W1 + relu
    k_aggh<<<gN16, TB>>>();           // layer 2 aggregation (64-dim)
    k_gemm2<<<gGemm, TB>>>(W2, b2);   // W2 + bias + relu + fused pool

    k_out<<<gG, TB>>>((float4*)d_out);
}